// round 6
// baseline (speedup 1.0000x reference)
#include <cuda_runtime.h>
#include <math.h>
#include <cstdint>

#define D      256
#define R      16
#define N0     8192
#define L      6
#define NL     8192
#define TOTAL  (N0 + L * NL)   // 57344
#define EVAL_BLOCKS 224

#define K1 512
#define K2 256

// ---------------- scratch (device globals; no allocation) ----------------
__device__ float g_store[(size_t)TOTAL * D];       // node embeddings fp32
__device__ float g_H[(size_t)NL * D];              // hidden after relu(GEMM1)
__device__ float g_Wt1[(size_t)R * D * K1];        // W1^T, k-interleaved: [R][n][K]
__device__ float g_Wt2[(size_t)R * D * K2];        // W2^T, k-interleaved
__device__ float g_partials[EVAL_BLOCKS * 5];

__device__ __forceinline__ uint32_t smem_to_u32(const void* p) {
    uint32_t a;
    asm("{ .reg .u64 t; cvta.to.shared.u64 t, %1; cvt.u32.u64 %0, t; }" : "=r"(a) : "l"(p));
    return a;
}

// ---------------- init: store[:N0] = init_table[thax_ids] ----------------
__global__ void init_gather(const int* __restrict__ thax,
                            const float* __restrict__ table) {
    int t = blockIdx.x * blockDim.x + threadIdx.x;
    int row = t >> 6, c = t & 63;
    if (row < N0) {
        int tid_ = thax[row];
        ((float4*)g_store)[(size_t)row * 64 + c] =
            ((const float4*)(table + (size_t)tid_ * D))[c];
    }
}

// ---------------- weight transpose + k-interleave ----------------
// W[R][K][256] -> Wt[R][256(n)][K storage]; within each 16-k group the value
// for k is stored at pos(k) = (k&3)*4 + (k>>2).
template<int K, bool FIRST>
__global__ void transpose_w(const float* __restrict__ W) {
    __shared__ float tile[32][33];
    float* Wt = FIRST ? g_Wt1 : g_Wt2;
    int r = blockIdx.z;
    int k0 = blockIdx.x * 32, nb = blockIdx.y * 32;
    int tx = threadIdx.x, ty = threadIdx.y;
    const float* Wr = W + (size_t)r * K * D;
    float* Wtr = Wt + (size_t)r * D * K;
#pragma unroll
    for (int i = ty; i < 32; i += 8)
        tile[i][tx] = Wr[(size_t)(k0 + i) * D + nb + tx];
    __syncthreads();
    int gl = tx >> 4, p = tx & 15;
    int kl = (p & 3) * 4 + (p >> 2);          // inverse of pos()
#pragma unroll
    for (int i = ty; i < 32; i += 8)
        Wtr[(size_t)(nb + i) * K + k0 + gl * 16 + p] = tile[gl * 16 + kl][i];
}

// ---------------- tensor-core grouped GEMM (2-stage, BK=32, N-split) ----------------
// FIRST: g_H[m, n0:n0+128] = relu(gather(par->g_store)[64xK1] @ W1[r] + b1)
// else : g_store[N0+l*NL + m, n0:..] = g_H @ W2[r] + b2
// CTA: 128 thr = 4 warps (2m x 2n), BM=64, BN=128, warp tile 32x64.
// smem: A 2 stages x 64x32 (two 16-k subtiles, row stride 16) = 16KB
//       B 2 stages x 128x32 (same subtile layout) = 32KB   -> 48KB static
template<int K, bool FIRST>
__global__ void __launch_bounds__(128)
gemm_mma(const float* __restrict__ bias, const int* __restrict__ par, int layer) {
    constexpr int NIT = K / 32;
    __shared__ float smf[12288];     // [0,4096) A stages, [4096,12288) B stages
    const uint32_t smem_u32 = smem_to_u32(smf);

    const int tid  = threadIdx.x;
    const int lane = tid & 31;
    const int wid  = tid >> 5;
    const int g    = lane >> 2, t4 = lane & 3;
    const int warp_m = wid >> 1, warp_n = wid & 1;
    const int m0 = blockIdx.x * 64;
    const int n0 = blockIdx.y * 128;
    const int r  = m0 >> 9;

    // ---- loader constants: A chunks c = tid + 128*i (i<4): row=c>>3, sub=tid&7 ----
    const int sub   = tid & 7;          // k-chunk (4 floats) within 32
    const int ksub  = sub >> 2;         // 16-k subtile
    const int c4    = sub & 3;          // chunk within 16-k group
    int arow[4];
    const float* ap0[4];
    const float* ap1[4];
#pragma unroll
    for (int i = 0; i < 4; i++) {
        arow[i] = (tid >> 3) + 16 * i;
        int m = m0 + arow[i];
        if (FIRST) {
            ap0[i] = g_store + (size_t)par[2 * m] * D;
            ap1[i] = g_store + (size_t)par[2 * m + 1] * D;
        } else {
            ap0[i] = g_H + (size_t)m * D;
        }
    }
    const float* Wtr = (FIRST ? g_Wt1 : g_Wt2) + ((size_t)r * D + n0) * K;

    auto loadA = [&](int s, float4* v) {
        int gk = s * 32 + sub * 4;
#pragma unroll
        for (int i = 0; i < 4; i++) {
            const float* src;
            if (FIRST) src = (gk < D) ? (ap0[i] + gk) : (ap1[i] + gk - D);
            else       src = ap0[i] + gk;
            v[i] = *(const float4*)src;
        }
    };
    auto stsA = [&](int s, const float4* v) {
#pragma unroll
        for (int i = 0; i < 4; i++) {
            float* d = smf + (s & 1) * 2048 + ksub * 1024 + arow[i] * 16 + c4;
            d[0] = v[i].x; d[4] = v[i].y; d[8] = v[i].z; d[12] = v[i].w;
        }
    };
    auto issueB = [&](int s) {
#pragma unroll
        for (int j = 0; j < 8; j++) {
            int row = (tid >> 3) + 16 * j;
            const float* src = Wtr + (size_t)row * K + s * 32 + sub * 4;
            uint32_t dst = smem_u32 +
                (uint32_t)(4096 + (s & 1) * 4096 + ksub * 2048 + row * 16 + c4 * 4) * 4u;
            asm volatile("cp.async.cg.shared.global [%0], [%1], 16;" :: "r"(dst), "l"(src));
        }
    };

    float acc[2][8][4];
#pragma unroll
    for (int mt = 0; mt < 2; mt++)
#pragma unroll
        for (int nt = 0; nt < 8; nt++)
#pragma unroll
            for (int c = 0; c < 4; c++) acc[mt][nt][c] = 0.f;

    // one 16-k subtile of one stage: warp tile 32x64 -> 32 HMMA
    auto tile_mma = [&](const float* Ab, const float* Bb) {
        float4 Ar[2][2];
        float4 Br[8];
#pragma unroll
        for (int mt = 0; mt < 2; mt++)
#pragma unroll
            for (int h = 0; h < 2; h++)
                Ar[mt][h] = *(const float4*)(Ab + (mt * 16 + h * 8) * 16);
#pragma unroll
        for (int nt = 0; nt < 8; nt++)
            Br[nt] = *(const float4*)(Bb + nt * 128);
#pragma unroll
        for (int h = 0; h < 2; h++) {
#pragma unroll
            for (int mt = 0; mt < 2; mt++) {
                uint32_t a0, a1, a2, a3;
                if (h == 0) {
                    a0 = __float_as_uint(Ar[mt][0].x); a1 = __float_as_uint(Ar[mt][1].x);
                    a2 = __float_as_uint(Ar[mt][0].y); a3 = __float_as_uint(Ar[mt][1].y);
                } else {
                    a0 = __float_as_uint(Ar[mt][0].z); a1 = __float_as_uint(Ar[mt][1].z);
                    a2 = __float_as_uint(Ar[mt][0].w); a3 = __float_as_uint(Ar[mt][1].w);
                }
#pragma unroll
                for (int nt = 0; nt < 8; nt++) {
                    uint32_t b0, b1;
                    if (h == 0) { b0 = __float_as_uint(Br[nt].x); b1 = __float_as_uint(Br[nt].y); }
                    else        { b0 = __float_as_uint(Br[nt].z); b1 = __float_as_uint(Br[nt].w); }
                    asm volatile(
                        "mma.sync.aligned.m16n8k8.row.col.f32.tf32.tf32.f32 "
                        "{%0,%1,%2,%3}, {%4,%5,%6,%7}, {%8,%9}, {%0,%1,%2,%3};"
                        : "+f"(acc[mt][nt][0]), "+f"(acc[mt][nt][1]),
                          "+f"(acc[mt][nt][2]), "+f"(acc[mt][nt][3])
                        : "r"(a0), "r"(a1), "r"(a2), "r"(a3), "r"(b0), "r"(b1));
                }
            }
        }
    };

    // ---- prologue ----
    float4 aReg[4];
    loadA(0, aReg);
    stsA(0, aReg);
    issueB(0); asm volatile("cp.async.commit_group;");
    loadA(1, aReg);

    // ---- mainloop ----
    for (int it = 0; it < NIT; it++) {
        __syncthreads();                       // frees buffer (it+1)&1; makes stsA(it) visible
        if (it + 1 < NIT) {
            stsA(it + 1, aReg);
            issueB(it + 1); asm volatile("cp.async.commit_group;");
            if (it + 2 < NIT) loadA(it + 2, aReg);
            asm volatile("cp.async.wait_group 1;");
        } else {
            asm volatile("cp.async.wait_group 0;");
        }
#pragma unroll
        for (int ks = 0; ks < 2; ks++) {
            const float* Ab = smf + (it & 1) * 2048 + ks * 1024
                            + (warp_m * 32 + g) * 16 + t4 * 4;
            const float* Bb = smf + 4096 + (it & 1) * 4096 + ks * 2048
                            + (warp_n * 64 + g) * 16 + t4 * 4;
            tile_mma(Ab, Bb);
        }
    }

    // ---- epilogue: bias (+relu for GEMM1), write out ----
    float* Cbase = FIRST ? g_H : (g_store + (size_t)(N0 + layer * NL) * D);
    const float* br = bias + r * D + n0;
#pragma unroll
    for (int mt = 0; mt < 2; mt++) {
        int mr0 = m0 + warp_m * 32 + mt * 16 + g;
#pragma unroll
        for (int nt = 0; nt < 8; nt++) {
            int col = warp_n * 64 + nt * 8 + 2 * t4;
            float bx = br[col], by = br[col + 1];
            float2 v0, v1;
            v0.x = acc[mt][nt][0] + bx;  v0.y = acc[mt][nt][1] + by;
            v1.x = acc[mt][nt][2] + bx;  v1.y = acc[mt][nt][3] + by;
            if (FIRST) {
                v0.x = fmaxf(v0.x, 0.f); v0.y = fmaxf(v0.y, 0.f);
                v1.x = fmaxf(v1.x, 0.f); v1.y = fmaxf(v1.y, 0.f);
            }
            *(float2*)(Cbase + (size_t)mr0 * D + n0 + col)       = v0;
            *(float2*)(Cbase + (size_t)(mr0 + 8) * D + n0 + col) = v1;
        }
    }
}

// ---------------- eval + loss (deterministic two-stage reduction) ----------------
__device__ __forceinline__ float softplusf(float x) {
    return fmaxf(x, 0.f) + log1pf(expf(-fabsf(x)));
}

__global__ void __launch_bounds__(256)
eval_partial(const float* __restrict__ pos_vals, const float* __restrict__ neg_vals,
             const float* __restrict__ eval_w, const float* __restrict__ eval_b,
             const float* __restrict__ pos_weight) {
    __shared__ float red[8][5];
    const int lane = threadIdx.x & 31, warp = threadIdx.x >> 5;
    const int gw = blockIdx.x * 8 + warp;

    float w[8];
#pragma unroll
    for (int j = 0; j < 8; j++) w[j] = eval_w[lane + 32 * j];
    const float eb = *eval_b;
    const float pw = *pos_weight;

    float loss = 0.f, posOK = 0.f, negOK = 0.f, posTot = 0.f, negTot = 0.f;

    for (int node = gw; node < TOTAL; node += EVAL_BLOCKS * 8) {
        const float* row = g_store + (size_t)node * D;
        float s = 0.f;
#pragma unroll
        for (int j = 0; j < 8; j++) s += row[lane + 32 * j] * w[j];
#pragma unroll
        for (int off = 16; off; off >>= 1) s += __shfl_xor_sync(0xffffffffu, s, off);
        if (lane == 0) {
            float x = s + eb;
            float pv = pos_vals[node], nv = neg_vals[node];
            float tot = pv + nv;
            if (tot > 0.f) {
                float tgt = pv / fmaxf(tot, 1e-9f);
                float bce = pw * tgt * softplusf(-x) + (1.f - tgt) * softplusf(x);
                loss += tot * bce;
                posTot += pv; negTot += nv;
                if (x >= 0.f) posOK += pv; else negOK += nv;
            }
        }
    }
    if (lane == 0) {
        red[warp][0] = loss; red[warp][1] = posOK; red[warp][2] = negOK;
        red[warp][3] = posTot; red[warp][4] = negTot;
    }
    __syncthreads();
    if (threadIdx.x < 5) {
        float t = 0.f;
        for (int i = 0; i < 8; i++) t += red[i][threadIdx.x];
        g_partials[blockIdx.x * 5 + threadIdx.x] = t;
    }
}

__global__ void final_reduce(float* __restrict__ out, int out_size) {
    float s[5] = {0.f, 0.f, 0.f, 0.f, 0.f};
    for (int i = threadIdx.x; i < EVAL_BLOCKS; i += 32)
#pragma unroll
        for (int c = 0; c < 5; c++) s[c] += g_partials[i * 5 + c];
#pragma unroll
    for (int c = 0; c < 5; c++)
#pragma unroll
        for (int off = 16; off; off >>= 1)
            s[c] += __shfl_xor_sync(0xffffffffu, s[c], off);
    if (threadIdx.x == 0) {
        float loss = s[0], posOK = s[1], negOK = s[2], posTot = s[3], negTot = s[4];
        float pos_rate = (posTot > 0.f) ? posOK / fmaxf(posTot, 1e-9f) : 1.f;
        float neg_rate = (negTot > 0.f) ? negOK / fmaxf(negTot, 1e-9f) : 1.f;
        if (out_size >= 1) out[0] = loss;
        if (out_size >= 2) out[1] = pos_rate;
        if (out_size >= 3) out[2] = neg_rate;
    }
}

// ---------------- launch ----------------
extern "C" void kernel_launch(void* const* d_in, const int* in_sizes, int n_in,
                              void* d_out, int out_size) {
    const int*   thax       = (const int*)  d_in[0];
    const int*   par_idx    = (const int*)  d_in[1];
    const float* pos_vals   = (const float*)d_in[2];
    const float* neg_vals   = (const float*)d_in[3];
    const float* init_table = (const float*)d_in[4];
    const float* W1         = (const float*)d_in[5];
    const float* b1         = (const float*)d_in[6];
    const float* W2         = (const float*)d_in[7];
    const float* b2         = (const float*)d_in[8];
    const float* eval_w     = (const float*)d_in[9];
    const float* eval_b     = (const float*)d_in[10];
    const float* pos_weight = (const float*)d_in[11];
    float* out = (float*)d_out;

    init_gather<<<(N0 * 64) / 256, 256>>>(thax, init_table);
    transpose_w<K1, true ><<<dim3(K1 / 32, D / 32, R), dim3(32, 8)>>>(W1);
    transpose_w<K2, false><<<dim3(K2 / 32, D / 32, R), dim3(32, 8)>>>(W2);

    for (int l = 0; l < L; l++) {
        gemm_mma<K1, true ><<<dim3(NL / 64, 2), 128>>>(
            b1, par_idx + (size_t)l * NL * 2, l);
        gemm_mma<K2, false><<<dim3(NL / 64, 2), 128>>>(
            b2, nullptr, l);
    }

    eval_partial<<<EVAL_BLOCKS, 256>>>(pos_vals, neg_vals, eval_w, eval_b, pos_weight);
    final_reduce<<<1, 32>>>(out, out_size);
}

// round 7
// speedup vs baseline: 1.3893x; 1.3893x over previous
#include <cuda_runtime.h>
#include <cuda_fp16.h>
#include <math.h>
#include <cstdint>

#define D      256
#define R      16
#define N0     8192
#define L      6
#define NL     8192
#define TOTAL  (N0 + L * NL)   // 57344
#define EVAL_BLOCKS 224

#define K1 512
#define K2 256

// ---------------- scratch (device globals; no allocation) ----------------
__device__ float  g_store[(size_t)TOTAL * D];     // fp32 embeddings (eval)
__device__ __half g_storeh[(size_t)TOTAL * D];    // fp16 k-interleaved mirror
__device__ __half g_Hh[(size_t)NL * D];           // hidden, fp16 interleaved
__device__ __half g_W1h[(size_t)R * D * K1];      // W1^T fp16 interleaved [R][n][K]
__device__ __half g_W2h[(size_t)R * D * K2];
__device__ float  g_partials[EVAL_BLOCKS * 5];

__device__ __forceinline__ uint32_t smem_to_u32(const void* p) {
    uint32_t a;
    asm("{ .reg .u64 t; cvta.to.shared.u64 t, %1; cvt.u32.u64 %0, t; }" : "=r"(a) : "l"(p));
    return a;
}

// interleave position of k within a 32-k group so that thread t4's fragment
// halves {2t4,2t4+1,2t4+8,2t4+9} (x both 16-k steps) are 16B contiguous:
// pos = p*8 + g16*4 + hi*2 + q  (p=(k>>1)&3, g16=k>>4, hi=(k>>3)&1, q=k&1)
__device__ __forceinline__ int pos32(int k5) {
    return ((k5 >> 1) & 3) * 8 + (k5 >> 4) * 4 + ((k5 >> 3) & 1) * 2 + (k5 & 1);
}

// ---------------- init: fp32 + interleaved fp16 ----------------
__global__ void init_gather(const int* __restrict__ thax,
                            const float* __restrict__ table) {
    int t = blockIdx.x * blockDim.x + threadIdx.x;
    int row = t >> 6, c = t & 63;
    if (row < N0) {
        int tid_ = thax[row];
        float4 v = ((const float4*)(table + (size_t)tid_ * D))[c];
        ((float4*)g_store)[(size_t)row * 64 + c] = v;
        int k = c * 4;
        __half* hdst = g_storeh + (size_t)row * D + (k >> 5) * 32;
        int k5 = k & 31;
        *(__half2*)(hdst + pos32(k5))     = __floats2half2_rn(v.x, v.y);
        *(__half2*)(hdst + pos32(k5 + 2)) = __floats2half2_rn(v.z, v.w);
    }
}

// ---------------- weight convert: W[R][K][256] -> fp16 Wt[R][256][K] interleaved ----------------
template<int K, bool FIRST>
__global__ void convert_w(const float* __restrict__ W) {
    int r = blockIdx.y, kg = blockIdx.x, n = threadIdx.x;   // 256 threads = n
    __half loc[32];
    const float* Wr = W + ((size_t)r * K + kg * 32) * D + n;
#pragma unroll
    for (int k5 = 0; k5 < 32; k5++)
        loc[pos32(k5)] = __float2half_rn(Wr[(size_t)k5 * D]);
    __half* dst = (FIRST ? g_W1h : g_W2h) + ((size_t)(r * D + n)) * K + kg * 32;
    uint4* d4 = (uint4*)dst;
    const uint4* s4 = (const uint4*)loc;
#pragma unroll
    for (int i = 0; i < 4; i++) d4[i] = s4[i];
}

// ---------------- fp16 tensor-core grouped GEMM (4-stage, BK=32, N-split) ----------------
// FIRST: g_Hh[m, n0:+128] = relu(gather(par->g_storeh)[64xK1] @ W1[r] + b1)   (fp16 out)
// else : g_store/g_storeh[N0+l*NL+m, n0:+128] = g_Hh @ W2[r] + b2
// CTA: 128 thr = 4 warps (2m x 2n), BM=64, BN=128, warp tile 32x64, mma m16n8k16.
template<int K, bool FIRST>
__global__ void __launch_bounds__(128)
gemm_h(const float* __restrict__ bias, const int* __restrict__ par, int layer) {
    constexpr int NIT = K / 32;
    __shared__ __half sm[8192 + 16384];   // A: 4 x 64x32, B: 4 x 128x32 (49152 B)
    const uint32_t smem_u32 = smem_to_u32(sm);

    const int tid  = threadIdx.x;
    const int lane = tid & 31;
    const int wid  = tid >> 5;
    const int g    = lane >> 2, t4 = lane & 3;
    const int warp_m = wid >> 1, warp_n = wid & 1;
    const int m0 = blockIdx.x * 64;
    const int n0 = blockIdx.y * 128;
    const int r  = m0 >> 9;

    // ---- loader constants ----
    const int lc = tid & 3;          // 16B chunk within 32-k group (64B)
    const int lr = tid >> 2;         // base row 0..31
    const __half* aP0[2];
    const __half* aP1[2];
#pragma unroll
    for (int j = 0; j < 2; j++) {
        int m = m0 + lr + 32 * j;
        if (FIRST) {
            aP0[j] = g_storeh + (size_t)par[2 * m] * D;
            aP1[j] = g_storeh + (size_t)par[2 * m + 1] * D;
        } else {
            aP0[j] = g_Hh + (size_t)m * D;
        }
    }
    const __half* Wh = (FIRST ? g_W1h : g_W2h) + ((size_t)(r * D + n0)) * K;

    auto issue = [&](int s) {
#pragma unroll
        for (int j = 0; j < 2; j++) {                     // A: 2 x 16B per thread
            const __half* src;
            if (FIRST) src = ((s < 8) ? (aP0[j] + s * 32) : (aP1[j] + (s - 8) * 32)) + lc * 8;
            else       src = aP0[j] + s * 32 + lc * 8;
            uint32_t dst = smem_u32 +
                (uint32_t)((s & 3) * 2048 + (lr + 32 * j) * 32 + lc * 8) * 2u;
            asm volatile("cp.async.cg.shared.global [%0], [%1], 16;" :: "r"(dst), "l"(src));
        }
#pragma unroll
        for (int j = 0; j < 4; j++) {                     // B: 4 x 16B per thread
            int row = lr + 32 * j;
            const __half* src = Wh + (size_t)row * K + s * 32 + lc * 8;
            uint32_t dst = smem_u32 +
                (uint32_t)(8192 + (s & 3) * 4096 + row * 32 + lc * 8) * 2u;
            asm volatile("cp.async.cg.shared.global [%0], [%1], 16;" :: "r"(dst), "l"(src));
        }
    };

    float acc[2][8][4];
#pragma unroll
    for (int mt = 0; mt < 2; mt++)
#pragma unroll
        for (int nt = 0; nt < 8; nt++)
#pragma unroll
            for (int c = 0; c < 4; c++) acc[mt][nt][c] = 0.f;

    issue(0); asm volatile("cp.async.commit_group;");
    issue(1); asm volatile("cp.async.commit_group;");
    issue(2); asm volatile("cp.async.commit_group;");

    for (int it = 0; it < NIT; it++) {
        int rem = NIT - 1 - it;
        if (rem >= 2)      asm volatile("cp.async.wait_group 2;");
        else if (rem == 1) asm volatile("cp.async.wait_group 1;");
        else               asm volatile("cp.async.wait_group 0;");
        __syncthreads();
        if (it + 3 < NIT) { issue(it + 3); asm volatile("cp.async.commit_group;"); }

        const __half* As = sm + (it & 3) * 2048;
        const __half* Bs = sm + 8192 + (it & 3) * 4096;

        uint4 Av[2][2];
#pragma unroll
        for (int mt = 0; mt < 2; mt++) {
            int r0 = warp_m * 32 + mt * 16 + g;
            Av[mt][0] = *(const uint4*)(As + r0 * 32 + t4 * 8);
            Av[mt][1] = *(const uint4*)(As + (r0 + 8) * 32 + t4 * 8);
        }
        uint4 Bv[8];
#pragma unroll
        for (int nt = 0; nt < 8; nt++) {
            int cc = warp_n * 64 + nt * 8 + g;
            Bv[nt] = *(const uint4*)(Bs + cc * 32 + t4 * 8);
        }
        // two k16 steps: step0 uses .x/.y, step1 uses .z/.w
#pragma unroll
        for (int step = 0; step < 2; step++) {
#pragma unroll
            for (int mt = 0; mt < 2; mt++) {
                uint32_t a0 = step ? Av[mt][0].z : Av[mt][0].x;
                uint32_t a1 = step ? Av[mt][1].z : Av[mt][1].x;
                uint32_t a2 = step ? Av[mt][0].w : Av[mt][0].y;
                uint32_t a3 = step ? Av[mt][1].w : Av[mt][1].y;
#pragma unroll
                for (int nt = 0; nt < 8; nt++) {
                    uint32_t b0 = step ? Bv[nt].z : Bv[nt].x;
                    uint32_t b1 = step ? Bv[nt].w : Bv[nt].y;
                    asm volatile(
                        "mma.sync.aligned.m16n8k16.row.col.f32.f16.f16.f32 "
                        "{%0,%1,%2,%3}, {%4,%5,%6,%7}, {%8,%9}, {%0,%1,%2,%3};"
                        : "+f"(acc[mt][nt][0]), "+f"(acc[mt][nt][1]),
                          "+f"(acc[mt][nt][2]), "+f"(acc[mt][nt][3])
                        : "r"(a0), "r"(a1), "r"(a2), "r"(a3), "r"(b0), "r"(b1));
                }
            }
        }
    }

    // ---- epilogue ----
    const float* br = bias + r * D + n0;
#pragma unroll
    for (int mt = 0; mt < 2; mt++) {
        int mr0 = m0 + warp_m * 32 + mt * 16 + g;     // rows mr0, mr0+8
#pragma unroll
        for (int nt = 0; nt < 8; nt++) {
            int lcol = warp_n * 64 + nt * 8 + 2 * t4;
            int col  = n0 + lcol;
            float bx = br[lcol], by = br[lcol + 1];
            float x0 = acc[mt][nt][0] + bx, y0 = acc[mt][nt][1] + by;
            float x1 = acc[mt][nt][2] + bx, y1 = acc[mt][nt][3] + by;
            int hoff = (col >> 5) * 32 + pos32(col & 31);   // even -> half2 aligned
            if (FIRST) {
                x0 = fmaxf(x0, 0.f); y0 = fmaxf(y0, 0.f);
                x1 = fmaxf(x1, 0.f); y1 = fmaxf(y1, 0.f);
                *(__half2*)(g_Hh + (size_t)mr0 * D + hoff)       = __floats2half2_rn(x0, y0);
                *(__half2*)(g_Hh + (size_t)(mr0 + 8) * D + hoff) = __floats2half2_rn(x1, y1);
            } else {
                float*  C  = g_store  + (size_t)(N0 + layer * NL) * D;
                __half* Ch = g_storeh + (size_t)(N0 + layer * NL) * D;
                float2 v0 = {x0, y0}, v1 = {x1, y1};
                *(float2*)(C + (size_t)mr0 * D + col)        = v0;
                *(float2*)(C + (size_t)(mr0 + 8) * D + col)  = v1;
                *(__half2*)(Ch + (size_t)mr0 * D + hoff)       = __floats2half2_rn(x0, y0);
                *(__half2*)(Ch + (size_t)(mr0 + 8) * D + hoff) = __floats2half2_rn(x1, y1);
            }
        }
    }
}

// ---------------- eval + loss (deterministic two-stage reduction) ----------------
__device__ __forceinline__ float softplusf(float x) {
    return fmaxf(x, 0.f) + log1pf(expf(-fabsf(x)));
}

__global__ void __launch_bounds__(256)
eval_partial(const float* __restrict__ pos_vals, const float* __restrict__ neg_vals,
             const float* __restrict__ eval_w, const float* __restrict__ eval_b,
             const float* __restrict__ pos_weight) {
    __shared__ float red[8][5];
    const int lane = threadIdx.x & 31, warp = threadIdx.x >> 5;
    const int gw = blockIdx.x * 8 + warp;

    float w[8];
#pragma unroll
    for (int j = 0; j < 8; j++) w[j] = eval_w[lane + 32 * j];
    const float eb = *eval_b;
    const float pw = *pos_weight;

    float loss = 0.f, posOK = 0.f, negOK = 0.f, posTot = 0.f, negTot = 0.f;

    for (int node = gw; node < TOTAL; node += EVAL_BLOCKS * 8) {
        const float* row = g_store + (size_t)node * D;
        float s = 0.f;
#pragma unroll
        for (int j = 0; j < 8; j++) s += row[lane + 32 * j] * w[j];
#pragma unroll
        for (int off = 16; off; off >>= 1) s += __shfl_xor_sync(0xffffffffu, s, off);
        if (lane == 0) {
            float x = s + eb;
            float pv = pos_vals[node], nv = neg_vals[node];
            float tot = pv + nv;
            if (tot > 0.f) {
                float tgt = pv / fmaxf(tot, 1e-9f);
                float bce = pw * tgt * softplusf(-x) + (1.f - tgt) * softplusf(x);
                loss += tot * bce;
                posTot += pv; negTot += nv;
                if (x >= 0.f) posOK += pv; else negOK += nv;
            }
        }
    }
    if (lane == 0) {
        red[warp][0] = loss; red[warp][1] = posOK; red[warp][2] = negOK;
        red[warp][3] = posTot; red[warp][4] = negTot;
    }
    __syncthreads();
    if (threadIdx.x < 5) {
        float t = 0.f;
        for (int i = 0; i < 8; i++) t += red[i][threadIdx.x];
        g_partials[blockIdx.x * 5 + threadIdx.x] = t;
    }
}

__global__ void final_reduce(float* __restrict__ out, int out_size) {
    float s[5] = {0.f, 0.f, 0.f, 0.f, 0.f};
    for (int i = threadIdx.x; i < EVAL_BLOCKS; i += 32)
#pragma unroll
        for (int c = 0; c < 5; c++) s[c] += g_partials[i * 5 + c];
#pragma unroll
    for (int c = 0; c < 5; c++)
#pragma unroll
        for (int off = 16; off; off >>= 1)
            s[c] += __shfl_xor_sync(0xffffffffu, s[c], off);
    if (threadIdx.x == 0) {
        float loss = s[0], posOK = s[1], negOK = s[2], posTot = s[3], negTot = s[4];
        float pos_rate = (posTot > 0.f) ? posOK / fmaxf(posTot, 1e-9f) : 1.f;
        float neg_rate = (negTot > 0.f) ? negOK / fmaxf(negTot, 1e-9f) : 1.f;
        if (out_size >= 1) out[0] = loss;
        if (out_size >= 2) out[1] = pos_rate;
        if (out_size >= 3) out[2] = neg_rate;
    }
}

// ---------------- launch ----------------
extern "C" void kernel_launch(void* const* d_in, const int* in_sizes, int n_in,
                              void* d_out, int out_size) {
    const int*   thax       = (const int*)  d_in[0];
    const int*   par_idx    = (const int*)  d_in[1];
    const float* pos_vals   = (const float*)d_in[2];
    const float* neg_vals   = (const float*)d_in[3];
    const float* init_table = (const float*)d_in[4];
    const float* W1         = (const float*)d_in[5];
    const float* b1         = (const float*)d_in[6];
    const float* W2         = (const float*)d_in[7];
    const float* b2         = (const float*)d_in[8];
    const float* eval_w     = (const float*)d_in[9];
    const float* eval_b     = (const float*)d_in[10];
    const float* pos_weight = (const float*)d_in[11];
    float* out = (float*)d_out;

    init_gather<<<(N0 * 64) / 256, 256>>>(thax, init_table);
    convert_w<K1, true ><<<dim3(K1 / 32, R), 256>>>(W1);
    convert_w<K2, false><<<dim3(K2 / 32, R), 256>>>(W2);

    for (int l = 0; l < L; l++) {
        gemm_h<K1, true ><<<dim3(NL / 64, 2), 128>>>(
            b1, par_idx + (size_t)l * NL * 2, l);
        gemm_h<K2, false><<<dim3(NL / 64, 2), 128>>>(
            b2, nullptr, l);
    }

    eval_partial<<<EVAL_BLOCKS, 256>>>(pos_vals, neg_vals, eval_w, eval_b, pos_weight);
    final_reduce<<<1, 32>>>(out, out_size);
}